// round 10
// baseline (speedup 1.0000x reference)
#include <cuda_runtime.h>
#include <cuda_fp16.h>
#include <math.h>
#include <cstdint>

#define TT 8192
#define HH 2048
#define NCHUNK 64
#define CLEN 128

// GEMM tiling: CTA 256x128, 8 warps of 64x64
#define BM 256
#define BN 128
#define BKE 64               // K elements per stage (fp16)
#define LDA 72               // row stride in elements (pad 8 -> 144B, conflict-free ldmatrix)
#define A_TILE_ELEMS (BM * LDA)
#define B_TILE_ELEMS (BN * LDA)
#define STAGE_BYTES ((A_TILE_ELEMS + B_TILE_ELEMS) * 2)   // 55296
#define NSTAGE 3
#define GSMEM (NSTAGE * STAGE_BYTES)       // 165888
#define KITER (HH / BKE)                   // 32

// ---------------- scratch (device globals; allocation-free) ----------------
__device__ float g_k[TT * HH];
__device__ float g_v[TT * HH];
__device__ float g_r[TT * HH];
__device__ __half g_ax[3][TT * HH];   // mixed activations fp16 (k,v,r)
__device__ __half g_wt[4][HH * HH];   // W^T fp16 (k,v,r,o)
__device__ __half g_rw[TT * HH];      // r*wkv fp16
__device__ float g_Sa[NCHUNK * HH];
__device__ float g_Sb[NCHUNK * HH];
__device__ float g_Sm[NCHUNK * HH];
__device__ float g_Pa[NCHUNK * HH];
__device__ float g_Pb[NCHUNK * HH];
__device__ float g_Pp[NCHUNK * HH];

// ---------------- PTX helpers (plain sm_80-era: work on sm_103 target) ----------------
__device__ __forceinline__ uint32_t smem_u32(const void* p) {
    uint32_t a;
    asm("{ .reg .u64 t; cvta.to.shared.u64 t, %1; cvt.u32.u64 %0, t; }" : "=r"(a) : "l"(p));
    return a;
}

#define CP_ASYNC16(dst, src) \
    asm volatile("cp.async.cg.shared.global [%0], [%1], 16;" :: "r"(dst), "l"(src))
#define CP_COMMIT() asm volatile("cp.async.commit_group;" ::: "memory")
#define CP_WAIT1() asm volatile("cp.async.wait_group 1;" ::: "memory")
#define CP_WAIT0() asm volatile("cp.async.wait_group 0;" ::: "memory")

__device__ __forceinline__ void ldmx4(uint32_t* r, uint32_t addr) {
    asm volatile("ldmatrix.sync.aligned.m8n8.x4.shared.b16 {%0,%1,%2,%3}, [%4];"
                 : "=r"(r[0]), "=r"(r[1]), "=r"(r[2]), "=r"(r[3]) : "r"(addr));
}

__device__ __forceinline__ void mma16816(float* d, const uint32_t* a, uint32_t b0, uint32_t b1) {
    asm volatile("mma.sync.aligned.m16n8k16.row.col.f32.f16.f16.f32 "
                 "{%0,%1,%2,%3}, {%4,%5,%6,%7}, {%8,%9}, {%0,%1,%2,%3};"
                 : "+f"(d[0]), "+f"(d[1]), "+f"(d[2]), "+f"(d[3])
                 : "r"(a[0]), "r"(a[1]), "r"(a[2]), "r"(a[3]), "r"(b0), "r"(b1));
}

// ================= fp16 mma.sync GEMM =================
// out[M,N](f32) = act( A[M,K] @ B[N,K]^T ), A and B fp16.
// MODE 0: none; MODE 1: sigmoid; MODE 2: + addv
template <int MODE>
__global__ void __launch_bounds__(256, 1)
mmagemm(const __half* __restrict__ A, const __half* __restrict__ B,
        const float* __restrict__ addv, float* __restrict__ out)
{
    extern __shared__ __half sm[];
    const uint32_t sbase = smem_u32(sm);
    const int tid = threadIdx.x;
    const int wid = tid >> 5, lid = tid & 31;
    const int row0 = blockIdx.y * BM;
    const int col0 = blockIdx.x * BN;
    const int wm = (wid >> 1) * 64;   // warp M offset: 0,64,128,192
    const int wn = (wid & 1) * 64;    // warp N offset: 0,64

    // per-thread cp.async coordinates: 8 chunks/row (64 elem), 32 rows per pass
    const int r0c = tid >> 3;            // base row (0..31)
    const int c16 = tid & 7;             // 16B chunk within row

    // ldmatrix lane addressing
    const int lrow = lid & 15;
    const int khalf = (lid >> 4) * 8;

    float acc[4][8][4];
#pragma unroll
    for (int mi = 0; mi < 4; ++mi)
#pragma unroll
        for (int ni = 0; ni < 8; ++ni)
#pragma unroll
            for (int j = 0; j < 4; ++j) acc[mi][ni][j] = 0.f;

    auto load_stage = [&](int buf, int it) {
        const int kt = it * BKE;
        const uint32_t sA = sbase + buf * STAGE_BYTES;
        const uint32_t sB = sA + A_TILE_ELEMS * 2;
#pragma unroll
        for (int i = 0; i < 8; ++i) {
            const int r = r0c + i * 32;
            const uint32_t so = (r * LDA + c16 * 8) * 2;
            CP_ASYNC16(sA + so, A + (size_t)(row0 + r) * HH + kt + c16 * 8);
        }
#pragma unroll
        for (int i = 0; i < 4; ++i) {
            const int r = r0c + i * 32;
            const uint32_t so = (r * LDA + c16 * 8) * 2;
            CP_ASYNC16(sB + so, B + (size_t)(col0 + r) * HH + kt + c16 * 8);
        }
        CP_COMMIT();
    };

    load_stage(0, 0);
    load_stage(1, 1);

    int buf = 0, nb = 2;
    for (int it = 0; it < KITER; ++it) {
        CP_WAIT1();
        __syncthreads();
        if (it + 2 < KITER) load_stage(nb, it + 2);

        const uint32_t sA = sbase + buf * STAGE_BYTES;
        const uint32_t sB = sA + A_TILE_ELEMS * 2;
#pragma unroll
        for (int k16 = 0; k16 < 4; ++k16) {
            uint32_t a[4][4], b[4][4];
#pragma unroll
            for (int mi = 0; mi < 4; ++mi)
                ldmx4(a[mi], sA + ((wm + 16 * mi + lrow) * LDA + k16 * 16 + khalf) * 2);
#pragma unroll
            for (int nt = 0; nt < 4; ++nt)
                ldmx4(b[nt], sB + ((wn + 16 * nt + lrow) * LDA + k16 * 16 + khalf) * 2);
#pragma unroll
            for (int mi = 0; mi < 4; ++mi)
#pragma unroll
                for (int nt = 0; nt < 4; ++nt) {
                    mma16816(acc[mi][2 * nt + 0], a[mi], b[nt][0], b[nt][2]);
                    mma16816(acc[mi][2 * nt + 1], a[mi], b[nt][1], b[nt][3]);
                }
        }
        buf = (buf + 1 == NSTAGE) ? 0 : buf + 1;
        nb = (nb + 1 == NSTAGE) ? 0 : nb + 1;
    }
    CP_WAIT0();

    // epilogue: direct fp32 stores from accumulator fragments
    const int erow = wm + (lid >> 2);
    const int ecol = wn + (lid & 3) * 2;
#pragma unroll
    for (int mi = 0; mi < 4; ++mi)
#pragma unroll
        for (int ni = 0; ni < 8; ++ni)
#pragma unroll
            for (int h = 0; h < 2; ++h) {
                const int r = row0 + erow + mi * 16 + h * 8;
                const int c = col0 + ecol + ni * 8;
                float2 v;
                v.x = acc[mi][ni][h * 2 + 0];
                v.y = acc[mi][ni][h * 2 + 1];
                if (MODE == 1) {
                    v.x = 1.f / (1.f + __expf(-v.x));
                    v.y = 1.f / (1.f + __expf(-v.y));
                }
                const size_t o = (size_t)r * HH + c;
                if (MODE == 2) {
                    float2 hv = *reinterpret_cast<const float2*>(addv + o);
                    v.x += hv.x; v.y += hv.y;
                }
                *reinterpret_cast<float2*>(out + o) = v;
            }
}

// ================= split / transpose prep =================
__global__ void __launch_bounds__(256)
split_acts(const float* __restrict__ hidden, const float* __restrict__ sx,
           const float* __restrict__ tmk, const float* __restrict__ tmv,
           const float* __restrict__ tmr)
{
    const int idx = blockIdx.x * 256 + threadIdx.x;  // float4 index
    const int h4 = idx & (HH / 4 - 1);
    float4 hv = reinterpret_cast<const float4*>(hidden)[idx];
    float4 pv = (idx >= HH / 4) ? reinterpret_cast<const float4*>(hidden)[idx - HH / 4]
                                : reinterpret_cast<const float4*>(sx)[h4];
    const float* tms[3] = {tmk, tmv, tmr};
#pragma unroll
    for (int p = 0; p < 3; ++p) {
        float4 mv = reinterpret_cast<const float4*>(tms[p])[h4];
        union { __half b[4]; uint2 u; } Hh;
        Hh.b[0] = __float2half_rn(fmaf(hv.x - pv.x, mv.x, pv.x));
        Hh.b[1] = __float2half_rn(fmaf(hv.y - pv.y, mv.y, pv.y));
        Hh.b[2] = __float2half_rn(fmaf(hv.z - pv.z, mv.z, pv.z));
        Hh.b[3] = __float2half_rn(fmaf(hv.w - pv.w, mv.w, pv.w));
        *reinterpret_cast<uint2*>(&g_ax[p][(size_t)idx * 4]) = Hh.u;
    }
}

// W[K,N] -> W^T[N,K] fp16, all 4 weights in one launch (grid.z selects W)
__global__ void __launch_bounds__(256)
wtrans4(const float* __restrict__ W0, const float* __restrict__ W1,
        const float* __restrict__ W2, const float* __restrict__ W3)
{
    __shared__ float ts[32][33];
    const int z = blockIdx.z;
    const float* W = (z == 0) ? W0 : (z == 1) ? W1 : (z == 2) ? W2 : W3;
    __half* T = &g_wt[z][0];
    const int n0 = blockIdx.x * 32, k0 = blockIdx.y * 32;
    const int tx = threadIdx.x, ty = threadIdx.y;  // 32 x 8
#pragma unroll
    for (int i = 0; i < 4; ++i)
        ts[ty + i * 8][tx] = W[(size_t)(k0 + ty + i * 8) * HH + n0 + tx];
    __syncthreads();
#pragma unroll
    for (int i = 0; i < 4; ++i) {
        const size_t o = (size_t)(n0 + ty + i * 8) * HH + k0 + tx;
        T[o] = __float2half_rn(ts[tx][ty + i * 8]);
    }
}

// ================= WKV chunked scan =================
__global__ void scan_phaseA(const float* __restrict__ td)
{
    int h = blockIdx.x * blockDim.x + threadIdx.x;
    int c = blockIdx.y;
    float w = -expf(td[h]);
    float a = 0.f, b = 0.f, p = -1e30f;
    int t0 = c * CLEN;
    for (int t = t0; t < t0 + CLEN; ++t) {
        int idx = t * HH + h;
        float kk = g_k[idx], vv = g_v[idx];
        float ww = w + p;
        float q = fmaxf(ww, kk);
        float e1 = __expf(ww - q);
        float e2 = __expf(kk - q);
        a = e1 * a + e2 * vv;
        b = e1 * b + e2;
        p = q;
    }
    g_Sa[c * HH + h] = a;
    g_Sb[c * HH + h] = b;
    g_Sm[c * HH + h] = p;
}

__global__ void scan_phaseB(const float* __restrict__ td,
                            const float* __restrict__ aa0, const float* __restrict__ bb0,
                            const float* __restrict__ pp0, const float* __restrict__ hidden,
                            float* __restrict__ out)
{
    int h = blockIdx.x * blockDim.x + threadIdx.x;
    float w = -expf(td[h]);
    float wL = w * (float)CLEN;
    float a = aa0[h], b = bb0[h], p = pp0[h];
    for (int c = 0; c < NCHUNK; ++c) {
        g_Pa[c * HH + h] = a;
        g_Pb[c * HH + h] = b;
        g_Pp[c * HH + h] = p;
        float m = g_Sm[c * HH + h];
        float pd = p + wL;
        float q = fmaxf(pd, m);
        float e1 = __expf(pd - q);
        float e2 = __expf(m - q);
        a = e1 * a + e2 * g_Sa[c * HH + h];
        b = e1 * b + e2 * g_Sb[c * HH + h];
        p = q;
    }
    out[TT * HH + h] = hidden[(TT - 1) * HH + h];
    out[TT * HH + HH + h] = a;
    out[TT * HH + 2 * HH + h] = b;
    out[TT * HH + 3 * HH + h] = p;
}

__global__ void scan_phaseC(const float* __restrict__ td, const float* __restrict__ tf)
{
    int h = blockIdx.x * blockDim.x + threadIdx.x;
    int c = blockIdx.y;
    float w = -expf(td[h]);
    float u = tf[h];
    float a = g_Pa[c * HH + h], b = g_Pb[c * HH + h], p = g_Pp[c * HH + h];
    int t0 = c * CLEN;
    for (int t = t0; t < t0 + CLEN; ++t) {
        int idx = t * HH + h;
        float kk = g_k[idx], vv = g_v[idx];
        float ww = u + kk;
        float q = fmaxf(p, ww);
        float e1 = __expf(p - q);
        float e2 = __expf(ww - q);
        float wkv = (e1 * a + e2 * vv) / (e1 * b + e2);
        g_rw[idx] = __float2half_rn(g_r[idx] * wkv);
        float ww2 = w + p;
        float q2 = fmaxf(ww2, kk);
        float f1 = __expf(ww2 - q2);
        float f2 = __expf(kk - q2);
        a = f1 * a + f2 * vv;
        b = f1 * b + f2;
        p = q2;
    }
}

extern "C" void kernel_launch(void* const* d_in, const int* in_sizes, int n_in,
                              void* d_out, int out_size)
{
    const float* hidden = (const float*)d_in[0];
    const float* sx     = (const float*)d_in[1];
    const float* aa     = (const float*)d_in[2];
    const float* bb     = (const float*)d_in[3];
    const float* pp     = (const float*)d_in[4];
    const float* td     = (const float*)d_in[5];
    const float* tf     = (const float*)d_in[6];
    const float* tmk    = (const float*)d_in[7];
    const float* tmv    = (const float*)d_in[8];
    const float* tmr    = (const float*)d_in[9];
    const float* Wk     = (const float*)d_in[10];
    const float* Wv     = (const float*)d_in[11];
    const float* Wr     = (const float*)d_in[12];
    const float* Wo     = (const float*)d_in[13];
    float* out = (float*)d_out;

    cudaFuncSetAttribute(mmagemm<0>, cudaFuncAttributeMaxDynamicSharedMemorySize, GSMEM);
    cudaFuncSetAttribute(mmagemm<1>, cudaFuncAttributeMaxDynamicSharedMemorySize, GSMEM);
    cudaFuncSetAttribute(mmagemm<2>, cudaFuncAttributeMaxDynamicSharedMemorySize, GSMEM);

    float *pk, *pv, *pr;
    cudaGetSymbolAddress((void**)&pk, g_k);
    cudaGetSymbolAddress((void**)&pv, g_v);
    cudaGetSymbolAddress((void**)&pr, g_r);
    __half *ax, *wt, *rw;
    cudaGetSymbolAddress((void**)&ax, g_ax);
    cudaGetSymbolAddress((void**)&wt, g_wt);
    cudaGetSymbolAddress((void**)&rw, g_rw);
    const size_t AS = (size_t)TT * HH;
    const size_t WS = (size_t)HH * HH;

    dim3 wgrid(HH / 32, HH / 32, 4), wblk(32, 8);
    wtrans4<<<wgrid, wblk>>>(Wk, Wv, Wr, Wo);
    split_acts<<<(TT * HH / 4) / 256, 256>>>(hidden, sx, tmk, tmv, tmr);

    dim3 gg(HH / BN, TT / BM);
    mmagemm<0><<<gg, 256, GSMEM>>>(ax + 0 * AS, wt + 0 * WS, nullptr, pk);
    mmagemm<0><<<gg, 256, GSMEM>>>(ax + 1 * AS, wt + 1 * WS, nullptr, pv);
    mmagemm<1><<<gg, 256, GSMEM>>>(ax + 2 * AS, wt + 2 * WS, nullptr, pr);

    dim3 sgrid(HH / 256, NCHUNK);
    scan_phaseA<<<sgrid, 256>>>(td);
    scan_phaseB<<<HH / 256, 256>>>(td, aa, bb, pp, hidden, out);
    scan_phaseC<<<sgrid, 256>>>(td, tf);

    mmagemm<2><<<gg, 256, GSMEM>>>(rw, wt + 3 * WS, hidden, out);
}

// round 11
// speedup vs baseline: 1.1475x; 1.1475x over previous
#include <cuda_runtime.h>
#include <cuda_fp16.h>
#include <math.h>
#include <cstdint>

#define TT 8192
#define HH 2048
#define NCHUNK 64
#define CLEN 128

// GEMM tiling (R8 config: best measured)
#define BM 128
#define BN 128
#define BKE 64               // K elements per stage (fp16)
#define LDA 72               // row stride in elements (pad 8 -> 144B, conflict-free ldmatrix)
#define TILE_ELEMS (128 * LDA)
#define STAGE_BYTES (2 * TILE_ELEMS * 2)   // A tile + B tile, fp16 (36864)
#define NSTAGE 3
#define GSMEM (NSTAGE * STAGE_BYTES)       // 110592 -> 2 CTAs/SM
#define KITER (HH / BKE)                   // 32

// ---------------- scratch (device globals; allocation-free) ----------------
__device__ float g_k[TT * HH];
__device__ float g_v[TT * HH];
__device__ float g_r[TT * HH];            // raw receptance (pre-sigmoid)
__device__ __half g_ax[3][TT * HH];       // mixed activations fp16 (k,v,r)
__device__ __half g_wt[4][HH * HH];       // W^T fp16 (k,v,r,o)
__device__ __half g_rw[TT * HH];          // sigmoid(r)*wkv fp16
__device__ float g_Sa[NCHUNK * HH];
__device__ float g_Sb[NCHUNK * HH];
__device__ float g_Sm[NCHUNK * HH];
__device__ float g_Pa[NCHUNK * HH];
__device__ float g_Pb[NCHUNK * HH];
__device__ float g_Pp[NCHUNK * HH];

// ---------------- PTX helpers (plain sm_80-era: work on sm_103 target) ----------------
__device__ __forceinline__ uint32_t smem_u32(const void* p) {
    uint32_t a;
    asm("{ .reg .u64 t; cvta.to.shared.u64 t, %1; cvt.u32.u64 %0, t; }" : "=r"(a) : "l"(p));
    return a;
}

#define CP_ASYNC16(dst, src) \
    asm volatile("cp.async.cg.shared.global [%0], [%1], 16;" :: "r"(dst), "l"(src))
#define CP_COMMIT() asm volatile("cp.async.commit_group;" ::: "memory")
#define CP_WAIT1() asm volatile("cp.async.wait_group 1;" ::: "memory")
#define CP_WAIT0() asm volatile("cp.async.wait_group 0;" ::: "memory")

__device__ __forceinline__ void ldmx4(uint32_t* r, uint32_t addr) {
    asm volatile("ldmatrix.sync.aligned.m8n8.x4.shared.b16 {%0,%1,%2,%3}, [%4];"
                 : "=r"(r[0]), "=r"(r[1]), "=r"(r[2]), "=r"(r[3]) : "r"(addr));
}

__device__ __forceinline__ void mma16816(float* d, const uint32_t* a, uint32_t b0, uint32_t b1) {
    asm volatile("mma.sync.aligned.m16n8k16.row.col.f32.f16.f16.f32 "
                 "{%0,%1,%2,%3}, {%4,%5,%6,%7}, {%8,%9}, {%0,%1,%2,%3};"
                 : "+f"(d[0]), "+f"(d[1]), "+f"(d[2]), "+f"(d[3])
                 : "r"(a[0]), "r"(a[1]), "r"(a[2]), "r"(a[3]), "r"(b0), "r"(b1));
}

// ---------------- shared GEMM mainloop (returns acc in-place) ----------------
struct GemmCtx {
    uint32_t sbase;
    int tid, wid, lid, wm, wn, r0c, c16, lrow, khalf;
};

__device__ __forceinline__ void gemm_main(
    const __half* __restrict__ A, const __half* __restrict__ B,
    int row0, int col0, const GemmCtx& cx, float acc[2][8][4])
{
#pragma unroll
    for (int mi = 0; mi < 2; ++mi)
#pragma unroll
        for (int ni = 0; ni < 8; ++ni)
#pragma unroll
            for (int j = 0; j < 4; ++j) acc[mi][ni][j] = 0.f;

    auto load_stage = [&](int buf, int it) {
        const int kt = it * BKE;
        const uint32_t sA = cx.sbase + buf * STAGE_BYTES;
        const uint32_t sB = sA + TILE_ELEMS * 2;
#pragma unroll
        for (int i = 0; i < 4; ++i) {
            const int r = cx.r0c + i * 32;
            const uint32_t so = (r * LDA + cx.c16 * 8) * 2;
            CP_ASYNC16(sA + so, A + (size_t)(row0 + r) * HH + kt + cx.c16 * 8);
            CP_ASYNC16(sB + so, B + (size_t)(col0 + r) * HH + kt + cx.c16 * 8);
        }
        CP_COMMIT();
    };

    load_stage(0, 0);
    load_stage(1, 1);

    int buf = 0, nb = 2;
    for (int it = 0; it < KITER; ++it) {
        CP_WAIT1();
        __syncthreads();
        if (it + 2 < KITER) load_stage(nb, it + 2);

        const uint32_t sA = cx.sbase + buf * STAGE_BYTES;
        const uint32_t sB = sA + TILE_ELEMS * 2;
#pragma unroll
        for (int k16 = 0; k16 < 4; ++k16) {
            uint32_t a[2][4], b[4][4];
#pragma unroll
            for (int mi = 0; mi < 2; ++mi)
                ldmx4(a[mi], sA + ((cx.wm + 16 * mi + cx.lrow) * LDA + k16 * 16 + cx.khalf) * 2);
#pragma unroll
            for (int nt = 0; nt < 4; ++nt)
                ldmx4(b[nt], sB + ((cx.wn + 16 * nt + cx.lrow) * LDA + k16 * 16 + cx.khalf) * 2);
#pragma unroll
            for (int mi = 0; mi < 2; ++mi)
#pragma unroll
                for (int nt = 0; nt < 4; ++nt) {
                    mma16816(acc[mi][2 * nt + 0], a[mi], b[nt][0], b[nt][2]);
                    mma16816(acc[mi][2 * nt + 1], a[mi], b[nt][1], b[nt][3]);
                }
        }
        buf = (buf + 1 == NSTAGE) ? 0 : buf + 1;
        nb = (nb + 1 == NSTAGE) ? 0 : nb + 1;
    }
    CP_WAIT0();
}

__device__ __forceinline__ GemmCtx make_ctx(const void* smem) {
    GemmCtx cx;
    cx.sbase = smem_u32(smem);
    cx.tid = threadIdx.x;
    cx.wid = cx.tid >> 5; cx.lid = cx.tid & 31;
    cx.wm = (cx.wid >> 1) * 32;
    cx.wn = (cx.wid & 1) * 64;
    cx.r0c = cx.tid >> 3;
    cx.c16 = cx.tid & 7;
    cx.lrow = cx.lid & 15;
    cx.khalf = (cx.lid >> 4) * 8;
    return cx;
}

// ================= fused k/v/r GEMM: grid.z selects which =================
__global__ void __launch_bounds__(256, 2)
mmagemm_kvr()
{
    extern __shared__ __half sm[];
    const GemmCtx cx = make_ctx(sm);
    const int z = blockIdx.z;
    const int row0 = blockIdx.y * BM;
    const int col0 = blockIdx.x * BN;
    const __half* A = &g_ax[z][0];
    const __half* B = &g_wt[z][0];
    float* out = (z == 0) ? g_k : (z == 1) ? g_v : g_r;

    float acc[2][8][4];
    gemm_main(A, B, row0, col0, cx, acc);

    const int erow = cx.wm + (cx.lid >> 2);
    const int ecol = cx.wn + (cx.lid & 3) * 2;
#pragma unroll
    for (int mi = 0; mi < 2; ++mi)
#pragma unroll
        for (int ni = 0; ni < 8; ++ni)
#pragma unroll
            for (int h = 0; h < 2; ++h) {
                const int r = row0 + erow + mi * 16 + h * 8;
                const int c = col0 + ecol + ni * 8;
                float2 v;
                v.x = acc[mi][ni][h * 2 + 0];
                v.y = acc[mi][ni][h * 2 + 1];
                *reinterpret_cast<float2*>(out + (size_t)r * HH + c) = v;
            }
}

// ================= final GEMM: out = hidden + rw @ Wo^T =================
__global__ void __launch_bounds__(256, 2)
mmagemm_out(const float* __restrict__ addv, float* __restrict__ out)
{
    extern __shared__ __half sm[];
    const GemmCtx cx = make_ctx(sm);
    const int row0 = blockIdx.y * BM;
    const int col0 = blockIdx.x * BN;

    float acc[2][8][4];
    gemm_main(&g_rw[0], &g_wt[3][0], row0, col0, cx, acc);

    const int erow = cx.wm + (cx.lid >> 2);
    const int ecol = cx.wn + (cx.lid & 3) * 2;
#pragma unroll
    for (int mi = 0; mi < 2; ++mi)
#pragma unroll
        for (int ni = 0; ni < 8; ++ni)
#pragma unroll
            for (int h = 0; h < 2; ++h) {
                const int r = row0 + erow + mi * 16 + h * 8;
                const int c = col0 + ecol + ni * 8;
                const size_t o = (size_t)r * HH + c;
                float2 hv = *reinterpret_cast<const float2*>(addv + o);
                float2 v;
                v.x = acc[mi][ni][h * 2 + 0] + hv.x;
                v.y = acc[mi][ni][h * 2 + 1] + hv.y;
                *reinterpret_cast<float2*>(out + o) = v;
            }
}

// ================= split / transpose prep =================
__global__ void __launch_bounds__(256)
split_acts(const float* __restrict__ hidden, const float* __restrict__ sx,
           const float* __restrict__ tmk, const float* __restrict__ tmv,
           const float* __restrict__ tmr)
{
    const int idx = blockIdx.x * 256 + threadIdx.x;  // float4 index
    const int h4 = idx & (HH / 4 - 1);
    float4 hv = reinterpret_cast<const float4*>(hidden)[idx];
    float4 pv = (idx >= HH / 4) ? reinterpret_cast<const float4*>(hidden)[idx - HH / 4]
                                : reinterpret_cast<const float4*>(sx)[h4];
    const float* tms[3] = {tmk, tmv, tmr};
#pragma unroll
    for (int p = 0; p < 3; ++p) {
        float4 mv = reinterpret_cast<const float4*>(tms[p])[h4];
        union { __half b[4]; uint2 u; } Hh;
        Hh.b[0] = __float2half_rn(fmaf(hv.x - pv.x, mv.x, pv.x));
        Hh.b[1] = __float2half_rn(fmaf(hv.y - pv.y, mv.y, pv.y));
        Hh.b[2] = __float2half_rn(fmaf(hv.z - pv.z, mv.z, pv.z));
        Hh.b[3] = __float2half_rn(fmaf(hv.w - pv.w, mv.w, pv.w));
        *reinterpret_cast<uint2*>(&g_ax[p][(size_t)idx * 4]) = Hh.u;
    }
}

// W[K,N] -> W^T[N,K] fp16, all 4 weights in one launch (grid.z selects W)
__global__ void __launch_bounds__(256)
wtrans4(const float* __restrict__ W0, const float* __restrict__ W1,
        const float* __restrict__ W2, const float* __restrict__ W3)
{
    __shared__ float ts[32][33];
    const int z = blockIdx.z;
    const float* W = (z == 0) ? W0 : (z == 1) ? W1 : (z == 2) ? W2 : W3;
    __half* T = &g_wt[z][0];
    const int n0 = blockIdx.x * 32, k0 = blockIdx.y * 32;
    const int tx = threadIdx.x, ty = threadIdx.y;  // 32 x 8
#pragma unroll
    for (int i = 0; i < 4; ++i)
        ts[ty + i * 8][tx] = W[(size_t)(k0 + ty + i * 8) * HH + n0 + tx];
    __syncthreads();
#pragma unroll
    for (int i = 0; i < 4; ++i) {
        const size_t o = (size_t)(n0 + ty + i * 8) * HH + k0 + tx;
        T[o] = __float2half_rn(ts[tx][ty + i * 8]);
    }
}

// ================= WKV chunked scan =================
__global__ void scan_phaseA(const float* __restrict__ td)
{
    int h = blockIdx.x * blockDim.x + threadIdx.x;
    int c = blockIdx.y;
    float w = -expf(td[h]);
    float a = 0.f, b = 0.f, p = -1e30f;
    int t0 = c * CLEN;
    for (int t = t0; t < t0 + CLEN; ++t) {
        int idx = t * HH + h;
        float kk = g_k[idx], vv = g_v[idx];
        float ww = w + p;
        float q = fmaxf(ww, kk);
        float e1 = __expf(ww - q);
        float e2 = __expf(kk - q);
        a = e1 * a + e2 * vv;
        b = e1 * b + e2;
        p = q;
    }
    g_Sa[c * HH + h] = a;
    g_Sb[c * HH + h] = b;
    g_Sm[c * HH + h] = p;
}

__global__ void scan_phaseB(const float* __restrict__ td,
                            const float* __restrict__ aa0, const float* __restrict__ bb0,
                            const float* __restrict__ pp0, const float* __restrict__ hidden,
                            float* __restrict__ out)
{
    int h = blockIdx.x * blockDim.x + threadIdx.x;
    float w = -expf(td[h]);
    float wL = w * (float)CLEN;
    float a = aa0[h], b = bb0[h], p = pp0[h];
    for (int c = 0; c < NCHUNK; ++c) {
        g_Pa[c * HH + h] = a;
        g_Pb[c * HH + h] = b;
        g_Pp[c * HH + h] = p;
        float m = g_Sm[c * HH + h];
        float pd = p + wL;
        float q = fmaxf(pd, m);
        float e1 = __expf(pd - q);
        float e2 = __expf(m - q);
        a = e1 * a + e2 * g_Sa[c * HH + h];
        b = e1 * b + e2 * g_Sb[c * HH + h];
        p = q;
    }
    out[TT * HH + h] = hidden[(TT - 1) * HH + h];
    out[TT * HH + HH + h] = a;
    out[TT * HH + 2 * HH + h] = b;
    out[TT * HH + 3 * HH + h] = p;
}

__global__ void scan_phaseC(const float* __restrict__ td, const float* __restrict__ tf)
{
    int h = blockIdx.x * blockDim.x + threadIdx.x;
    int c = blockIdx.y;
    float w = -expf(td[h]);
    float u = tf[h];
    float a = g_Pa[c * HH + h], b = g_Pb[c * HH + h], p = g_Pp[c * HH + h];
    int t0 = c * CLEN;
    for (int t = t0; t < t0 + CLEN; ++t) {
        int idx = t * HH + h;
        float kk = g_k[idx], vv = g_v[idx];
        float ww = u + kk;
        float q = fmaxf(p, ww);
        float e1 = __expf(p - q);
        float e2 = __expf(ww - q);
        float wkv = (e1 * a + e2 * vv) / (e1 * b + e2);
        float rr = 1.f / (1.f + __expf(-g_r[idx]));
        g_rw[idx] = __float2half_rn(rr * wkv);
        float ww2 = w + p;
        float q2 = fmaxf(ww2, kk);
        float f1 = __expf(ww2 - q2);
        float f2 = __expf(kk - q2);
        a = f1 * a + f2 * vv;
        b = f1 * b + f2;
        p = q2;
    }
}

extern "C" void kernel_launch(void* const* d_in, const int* in_sizes, int n_in,
                              void* d_out, int out_size)
{
    const float* hidden = (const float*)d_in[0];
    const float* sx     = (const float*)d_in[1];
    const float* aa     = (const float*)d_in[2];
    const float* bb     = (const float*)d_in[3];
    const float* pp     = (const float*)d_in[4];
    const float* td     = (const float*)d_in[5];
    const float* tf     = (const float*)d_in[6];
    const float* tmk    = (const float*)d_in[7];
    const float* tmv    = (const float*)d_in[8];
    const float* tmr    = (const float*)d_in[9];
    const float* Wk     = (const float*)d_in[10];
    const float* Wv     = (const float*)d_in[11];
    const float* Wr     = (const float*)d_in[12];
    const float* Wo     = (const float*)d_in[13];
    float* out = (float*)d_out;

    cudaFuncSetAttribute(mmagemm_kvr, cudaFuncAttributeMaxDynamicSharedMemorySize, GSMEM);
    cudaFuncSetAttribute(mmagemm_out, cudaFuncAttributeMaxDynamicSharedMemorySize, GSMEM);

    dim3 wgrid(HH / 32, HH / 32, 4), wblk(32, 8);
    wtrans4<<<wgrid, wblk>>>(Wk, Wv, Wr, Wo);
    split_acts<<<(TT * HH / 4) / 256, 256>>>(hidden, sx, tmk, tmv, tmr);

    dim3 gkvr(HH / BN, TT / BM, 3);
    mmagemm_kvr<<<gkvr, 256, GSMEM>>>();

    dim3 sgrid(HH / 256, NCHUNK);
    scan_phaseA<<<sgrid, 256>>>(td);
    scan_phaseB<<<HH / 256, 256>>>(td, aa, bb, pp, hidden, out);
    scan_phaseC<<<sgrid, 256>>>(td, tf);

    dim3 gg(HH / BN, TT / BM);
    mmagemm_out<<<gg, 256, GSMEM>>>(hidden, out);
}

// round 12
// speedup vs baseline: 1.1774x; 1.0261x over previous
#include <cuda_runtime.h>
#include <cuda_fp16.h>
#include <math.h>
#include <cstdint>

#define TT 8192
#define HH 2048
#define NCHUNK 64
#define CLEN 128

// GEMM tiling (R8 config: best measured)
#define BM 128
#define BN 128
#define BKE 64               // K elements per stage (fp16)
#define LDA 72               // row stride in elements (pad 8 -> 144B, conflict-free ldmatrix)
#define TILE_ELEMS (128 * LDA)
#define STAGE_BYTES (2 * TILE_ELEMS * 2)   // A tile + B tile, fp16 (36864)
#define NSTAGE 3
#define GSMEM (NSTAGE * STAGE_BYTES)       // 110592 -> 2 CTAs/SM
#define KITER (HH / BKE)                   // 32

// ---------------- scratch (device globals; allocation-free) ----------------
__device__ __half g_kh[TT * HH];          // k fp16
__device__ __half g_vh[TT * HH];          // v fp16
__device__ __half g_rh[TT * HH];          // raw receptance fp16 (pre-sigmoid)
__device__ __half g_ax[3][TT * HH];       // mixed activations fp16 (k,v,r)
__device__ __half g_wt[4][HH * HH];       // W^T fp16 (k,v,r,o)
__device__ __half g_rw[TT * HH];          // sigmoid(r)*wkv fp16
__device__ float g_Sa[NCHUNK * HH];
__device__ float g_Sb[NCHUNK * HH];
__device__ float g_Sm[NCHUNK * HH];
__device__ float g_Pa[NCHUNK * HH];
__device__ float g_Pb[NCHUNK * HH];
__device__ float g_Pp[NCHUNK * HH];

// ---------------- PTX helpers (plain sm_80-era: work on sm_103 target) ----------------
__device__ __forceinline__ uint32_t smem_u32(const void* p) {
    uint32_t a;
    asm("{ .reg .u64 t; cvta.to.shared.u64 t, %1; cvt.u32.u64 %0, t; }" : "=r"(a) : "l"(p));
    return a;
}

#define CP_ASYNC16(dst, src) \
    asm volatile("cp.async.cg.shared.global [%0], [%1], 16;" :: "r"(dst), "l"(src))
#define CP_COMMIT() asm volatile("cp.async.commit_group;" ::: "memory")
#define CP_WAIT1() asm volatile("cp.async.wait_group 1;" ::: "memory")
#define CP_WAIT0() asm volatile("cp.async.wait_group 0;" ::: "memory")

__device__ __forceinline__ void ldmx4(uint32_t* r, uint32_t addr) {
    asm volatile("ldmatrix.sync.aligned.m8n8.x4.shared.b16 {%0,%1,%2,%3}, [%4];"
                 : "=r"(r[0]), "=r"(r[1]), "=r"(r[2]), "=r"(r[3]) : "r"(addr));
}

__device__ __forceinline__ void mma16816(float* d, const uint32_t* a, uint32_t b0, uint32_t b1) {
    asm volatile("mma.sync.aligned.m16n8k16.row.col.f32.f16.f16.f32 "
                 "{%0,%1,%2,%3}, {%4,%5,%6,%7}, {%8,%9}, {%0,%1,%2,%3};"
                 : "+f"(d[0]), "+f"(d[1]), "+f"(d[2]), "+f"(d[3])
                 : "r"(a[0]), "r"(a[1]), "r"(a[2]), "r"(a[3]), "r"(b0), "r"(b1));
}

// ---------------- shared GEMM mainloop ----------------
struct GemmCtx {
    uint32_t sbase;
    int tid, wid, lid, wm, wn, r0c, c16, lrow, khalf;
};

__device__ __forceinline__ void gemm_main(
    const __half* __restrict__ A, const __half* __restrict__ B,
    int row0, int col0, const GemmCtx& cx, float acc[2][8][4])
{
#pragma unroll
    for (int mi = 0; mi < 2; ++mi)
#pragma unroll
        for (int ni = 0; ni < 8; ++ni)
#pragma unroll
            for (int j = 0; j < 4; ++j) acc[mi][ni][j] = 0.f;

    auto load_stage = [&](int buf, int it) {
        const int kt = it * BKE;
        const uint32_t sA = cx.sbase + buf * STAGE_BYTES;
        const uint32_t sB = sA + TILE_ELEMS * 2;
#pragma unroll
        for (int i = 0; i < 4; ++i) {
            const int r = cx.r0c + i * 32;
            const uint32_t so = (r * LDA + cx.c16 * 8) * 2;
            CP_ASYNC16(sA + so, A + (size_t)(row0 + r) * HH + kt + cx.c16 * 8);
            CP_ASYNC16(sB + so, B + (size_t)(col0 + r) * HH + kt + cx.c16 * 8);
        }
        CP_COMMIT();
    };

    load_stage(0, 0);
    load_stage(1, 1);

    int buf = 0, nb = 2;
    for (int it = 0; it < KITER; ++it) {
        CP_WAIT1();
        __syncthreads();
        if (it + 2 < KITER) load_stage(nb, it + 2);

        const uint32_t sA = cx.sbase + buf * STAGE_BYTES;
        const uint32_t sB = sA + TILE_ELEMS * 2;
#pragma unroll
        for (int k16 = 0; k16 < 4; ++k16) {
            uint32_t a[2][4], b[4][4];
#pragma unroll
            for (int mi = 0; mi < 2; ++mi)
                ldmx4(a[mi], sA + ((cx.wm + 16 * mi + cx.lrow) * LDA + k16 * 16 + cx.khalf) * 2);
#pragma unroll
            for (int nt = 0; nt < 4; ++nt)
                ldmx4(b[nt], sB + ((cx.wn + 16 * nt + cx.lrow) * LDA + k16 * 16 + cx.khalf) * 2);
#pragma unroll
            for (int mi = 0; mi < 2; ++mi)
#pragma unroll
                for (int nt = 0; nt < 4; ++nt) {
                    mma16816(acc[mi][2 * nt + 0], a[mi], b[nt][0], b[nt][2]);
                    mma16816(acc[mi][2 * nt + 1], a[mi], b[nt][1], b[nt][3]);
                }
        }
        buf = (buf + 1 == NSTAGE) ? 0 : buf + 1;
        nb = (nb + 1 == NSTAGE) ? 0 : nb + 1;
    }
    CP_WAIT0();
}

__device__ __forceinline__ GemmCtx make_ctx(const void* smem) {
    GemmCtx cx;
    cx.sbase = smem_u32(smem);
    cx.tid = threadIdx.x;
    cx.wid = cx.tid >> 5; cx.lid = cx.tid & 31;
    cx.wm = (cx.wid >> 1) * 32;
    cx.wn = (cx.wid & 1) * 64;
    cx.r0c = cx.tid >> 3;
    cx.c16 = cx.tid & 7;
    cx.lrow = cx.lid & 15;
    cx.khalf = (cx.lid >> 4) * 8;
    return cx;
}

// ================= fused k/v/r GEMM: grid.z selects which; fp16 output =================
__global__ void __launch_bounds__(256, 2)
mmagemm_kvr()
{
    extern __shared__ __half sm[];
    const GemmCtx cx = make_ctx(sm);
    const int z = blockIdx.z;
    const int row0 = blockIdx.y * BM;
    const int col0 = blockIdx.x * BN;
    const __half* A = &g_ax[z][0];
    const __half* B = &g_wt[z][0];
    __half* out = (z == 0) ? g_kh : (z == 1) ? g_vh : g_rh;

    float acc[2][8][4];
    gemm_main(A, B, row0, col0, cx, acc);

    const int erow = cx.wm + (cx.lid >> 2);
    const int ecol = cx.wn + (cx.lid & 3) * 2;
#pragma unroll
    for (int mi = 0; mi < 2; ++mi)
#pragma unroll
        for (int ni = 0; ni < 8; ++ni)
#pragma unroll
            for (int h = 0; h < 2; ++h) {
                const int r = row0 + erow + mi * 16 + h * 8;
                const int c = col0 + ecol + ni * 8;
                __half2 v = __floats2half2_rn(acc[mi][ni][h * 2 + 0], acc[mi][ni][h * 2 + 1]);
                *reinterpret_cast<__half2*>(out + (size_t)r * HH + c) = v;
            }
}

// ================= final GEMM: out = hidden + rw @ Wo^T =================
__global__ void __launch_bounds__(256, 2)
mmagemm_out(const float* __restrict__ addv, float* __restrict__ out)
{
    extern __shared__ __half sm[];
    const GemmCtx cx = make_ctx(sm);
    const int row0 = blockIdx.y * BM;
    const int col0 = blockIdx.x * BN;

    float acc[2][8][4];
    gemm_main(&g_rw[0], &g_wt[3][0], row0, col0, cx, acc);

    const int erow = cx.wm + (cx.lid >> 2);
    const int ecol = cx.wn + (cx.lid & 3) * 2;
#pragma unroll
    for (int mi = 0; mi < 2; ++mi)
#pragma unroll
        for (int ni = 0; ni < 8; ++ni)
#pragma unroll
            for (int h = 0; h < 2; ++h) {
                const int r = row0 + erow + mi * 16 + h * 8;
                const int c = col0 + ecol + ni * 8;
                const size_t o = (size_t)r * HH + c;
                float2 hv = *reinterpret_cast<const float2*>(addv + o);
                float2 v;
                v.x = acc[mi][ni][h * 2 + 0] + hv.x;
                v.y = acc[mi][ni][h * 2 + 1] + hv.y;
                *reinterpret_cast<float2*>(out + o) = v;
            }
}

// ================= split / transpose prep =================
__global__ void __launch_bounds__(256)
split_acts(const float* __restrict__ hidden, const float* __restrict__ sx,
           const float* __restrict__ tmk, const float* __restrict__ tmv,
           const float* __restrict__ tmr)
{
    const int idx = blockIdx.x * 256 + threadIdx.x;  // float4 index
    const int h4 = idx & (HH / 4 - 1);
    float4 hv = reinterpret_cast<const float4*>(hidden)[idx];
    float4 pv = (idx >= HH / 4) ? reinterpret_cast<const float4*>(hidden)[idx - HH / 4]
                                : reinterpret_cast<const float4*>(sx)[h4];
    const float* tms[3] = {tmk, tmv, tmr};
#pragma unroll
    for (int p = 0; p < 3; ++p) {
        float4 mv = reinterpret_cast<const float4*>(tms[p])[h4];
        union { __half b[4]; uint2 u; } Hh;
        Hh.b[0] = __float2half_rn(fmaf(hv.x - pv.x, mv.x, pv.x));
        Hh.b[1] = __float2half_rn(fmaf(hv.y - pv.y, mv.y, pv.y));
        Hh.b[2] = __float2half_rn(fmaf(hv.z - pv.z, mv.z, pv.z));
        Hh.b[3] = __float2half_rn(fmaf(hv.w - pv.w, mv.w, pv.w));
        *reinterpret_cast<uint2*>(&g_ax[p][(size_t)idx * 4]) = Hh.u;
    }
}

// W[K,N] -> W^T[N,K] fp16, all 4 weights in one launch (grid.z selects W)
__global__ void __launch_bounds__(256)
wtrans4(const float* __restrict__ W0, const float* __restrict__ W1,
        const float* __restrict__ W2, const float* __restrict__ W3)
{
    __shared__ float ts[32][33];
    const int z = blockIdx.z;
    const float* W = (z == 0) ? W0 : (z == 1) ? W1 : (z == 2) ? W2 : W3;
    __half* T = &g_wt[z][0];
    const int n0 = blockIdx.x * 32, k0 = blockIdx.y * 32;
    const int tx = threadIdx.x, ty = threadIdx.y;  // 32 x 8
#pragma unroll
    for (int i = 0; i < 4; ++i)
        ts[ty + i * 8][tx] = W[(size_t)(k0 + ty + i * 8) * HH + n0 + tx];
    __syncthreads();
#pragma unroll
    for (int i = 0; i < 4; ++i) {
        const size_t o = (size_t)(n0 + ty + i * 8) * HH + k0 + tx;
        T[o] = __float2half_rn(ts[tx][ty + i * 8]);
    }
}

// ================= WKV chunked scan (fp16 k/v/r inputs) =================
__global__ void scan_phaseA(const float* __restrict__ td)
{
    int h = blockIdx.x * blockDim.x + threadIdx.x;
    int c = blockIdx.y;
    float w = -expf(td[h]);
    float a = 0.f, b = 0.f, p = -1e30f;
    int t0 = c * CLEN;
    for (int t = t0; t < t0 + CLEN; ++t) {
        int idx = t * HH + h;
        float kk = __half2float(g_kh[idx]);
        float vv = __half2float(g_vh[idx]);
        float ww = w + p;
        float q = fmaxf(ww, kk);
        float e1 = __expf(ww - q);
        float e2 = __expf(kk - q);
        a = e1 * a + e2 * vv;
        b = e1 * b + e2;
        p = q;
    }
    g_Sa[c * HH + h] = a;
    g_Sb[c * HH + h] = b;
    g_Sm[c * HH + h] = p;
}

__global__ void scan_phaseB(const float* __restrict__ td,
                            const float* __restrict__ aa0, const float* __restrict__ bb0,
                            const float* __restrict__ pp0, const float* __restrict__ hidden,
                            float* __restrict__ out)
{
    int h = blockIdx.x * blockDim.x + threadIdx.x;
    float w = -expf(td[h]);
    float wL = w * (float)CLEN;
    float a = aa0[h], b = bb0[h], p = pp0[h];
    for (int c = 0; c < NCHUNK; ++c) {
        g_Pa[c * HH + h] = a;
        g_Pb[c * HH + h] = b;
        g_Pp[c * HH + h] = p;
        float m = g_Sm[c * HH + h];
        float pd = p + wL;
        float q = fmaxf(pd, m);
        float e1 = __expf(pd - q);
        float e2 = __expf(m - q);
        a = e1 * a + e2 * g_Sa[c * HH + h];
        b = e1 * b + e2 * g_Sb[c * HH + h];
        p = q;
    }
    out[TT * HH + h] = hidden[(TT - 1) * HH + h];
    out[TT * HH + HH + h] = a;
    out[TT * HH + 2 * HH + h] = b;
    out[TT * HH + 3 * HH + h] = p;
}

__global__ void scan_phaseC(const float* __restrict__ td, const float* __restrict__ tf)
{
    int h = blockIdx.x * blockDim.x + threadIdx.x;
    int c = blockIdx.y;
    float w = -expf(td[h]);
    float u = tf[h];
    float a = g_Pa[c * HH + h], b = g_Pb[c * HH + h], p = g_Pp[c * HH + h];
    int t0 = c * CLEN;
    for (int t = t0; t < t0 + CLEN; ++t) {
        int idx = t * HH + h;
        float kk = __half2float(g_kh[idx]);
        float vv = __half2float(g_vh[idx]);
        float ww = u + kk;
        float q = fmaxf(p, ww);
        float e1 = __expf(p - q);
        float e2 = __expf(ww - q);
        float wkv = (e1 * a + e2 * vv) / (e1 * b + e2);
        float rr = 1.f / (1.f + __expf(-__half2float(g_rh[idx])));
        g_rw[idx] = __float2half_rn(rr * wkv);
        float ww2 = w + p;
        float q2 = fmaxf(ww2, kk);
        float f1 = __expf(ww2 - q2);
        float f2 = __expf(kk - q2);
        a = f1 * a + f2 * vv;
        b = f1 * b + f2;
        p = q2;
    }
}

extern "C" void kernel_launch(void* const* d_in, const int* in_sizes, int n_in,
                              void* d_out, int out_size)
{
    const float* hidden = (const float*)d_in[0];
    const float* sx     = (const float*)d_in[1];
    const float* aa     = (const float*)d_in[2];
    const float* bb     = (const float*)d_in[3];
    const float* pp     = (const float*)d_in[4];
    const float* td     = (const float*)d_in[5];
    const float* tf     = (const float*)d_in[6];
    const float* tmk    = (const float*)d_in[7];
    const float* tmv    = (const float*)d_in[8];
    const float* tmr    = (const float*)d_in[9];
    const float* Wk     = (const float*)d_in[10];
    const float* Wv     = (const float*)d_in[11];
    const float* Wr     = (const float*)d_in[12];
    const float* Wo     = (const float*)d_in[13];
    float* out = (float*)d_out;

    cudaFuncSetAttribute(mmagemm_kvr, cudaFuncAttributeMaxDynamicSharedMemorySize, GSMEM);
    cudaFuncSetAttribute(mmagemm_out, cudaFuncAttributeMaxDynamicSharedMemorySize, GSMEM);

    dim3 wgrid(HH / 32, HH / 32, 4), wblk(32, 8);
    wtrans4<<<wgrid, wblk>>>(Wk, Wv, Wr, Wo);
    split_acts<<<(TT * HH / 4) / 256, 256>>>(hidden, sx, tmk, tmv, tmr);

    dim3 gkvr(HH / BN, TT / BM, 3);
    mmagemm_kvr<<<gkvr, 256, GSMEM>>>();

    dim3 sgrid(HH / 256, NCHUNK);
    scan_phaseA<<<sgrid, 256>>>(td);
    scan_phaseB<<<HH / 256, 256>>>(td, aa, bb, pp, hidden, out);
    scan_phaseC<<<sgrid, 256>>>(td, tf);

    dim3 gg(HH / BN, TT / BM);
    mmagemm_out<<<gg, 256, GSMEM>>>(hidden, out);
}

// round 13
// speedup vs baseline: 1.2263x; 1.0415x over previous
#include <cuda_runtime.h>
#include <cuda_fp16.h>
#include <math.h>
#include <cstdint>

#define TT 8192
#define HH 2048
#define NCHUNK 128
#define CLEN 64

// GEMM tiling (R8 config: best measured; smem-crossbar-bound floor)
#define BM 128
#define BN 128
#define BKE 64               // K elements per stage (fp16)
#define LDA 72               // row stride in elements (pad 8 -> 144B, conflict-free ldmatrix)
#define TILE_ELEMS (128 * LDA)
#define STAGE_BYTES (2 * TILE_ELEMS * 2)   // A tile + B tile, fp16 (36864)
#define NSTAGE 3
#define GSMEM (NSTAGE * STAGE_BYTES)       // 110592 -> 2 CTAs/SM
#define KITER (HH / BKE)                   // 32

// ---------------- scratch (device globals; allocation-free) ----------------
__device__ __half g_kh[TT * HH];          // k fp16
__device__ __half g_vh[TT * HH];          // v fp16
__device__ __half g_rh[TT * HH];          // raw receptance fp16 (pre-sigmoid)
__device__ __half g_ax[3][TT * HH];       // mixed activations fp16 (k,v,r)
__device__ __half g_wt[4][HH * HH];       // W^T fp16 (k,v,r,o)
__device__ __half g_rw[TT * HH];          // sigmoid(r)*wkv fp16
__device__ float g_Sa[NCHUNK * HH];
__device__ float g_Sb[NCHUNK * HH];
__device__ float g_Sm[NCHUNK * HH];
__device__ float g_Pa[NCHUNK * HH];
__device__ float g_Pb[NCHUNK * HH];
__device__ float g_Pp[NCHUNK * HH];

// ---------------- PTX helpers (plain sm_80-era: work on sm_103 target) ----------------
__device__ __forceinline__ uint32_t smem_u32(const void* p) {
    uint32_t a;
    asm("{ .reg .u64 t; cvta.to.shared.u64 t, %1; cvt.u32.u64 %0, t; }" : "=r"(a) : "l"(p));
    return a;
}

#define CP_ASYNC16(dst, src) \
    asm volatile("cp.async.cg.shared.global [%0], [%1], 16;" :: "r"(dst), "l"(src))
#define CP_COMMIT() asm volatile("cp.async.commit_group;" ::: "memory")
#define CP_WAIT1() asm volatile("cp.async.wait_group 1;" ::: "memory")
#define CP_WAIT0() asm volatile("cp.async.wait_group 0;" ::: "memory")

__device__ __forceinline__ void ldmx4(uint32_t* r, uint32_t addr) {
    asm volatile("ldmatrix.sync.aligned.m8n8.x4.shared.b16 {%0,%1,%2,%3}, [%4];"
                 : "=r"(r[0]), "=r"(r[1]), "=r"(r[2]), "=r"(r[3]) : "r"(addr));
}

__device__ __forceinline__ void mma16816(float* d, const uint32_t* a, uint32_t b0, uint32_t b1) {
    asm volatile("mma.sync.aligned.m16n8k16.row.col.f32.f16.f16.f32 "
                 "{%0,%1,%2,%3}, {%4,%5,%6,%7}, {%8,%9}, {%0,%1,%2,%3};"
                 : "+f"(d[0]), "+f"(d[1]), "+f"(d[2]), "+f"(d[3])
                 : "r"(a[0]), "r"(a[1]), "r"(a[2]), "r"(a[3]), "r"(b0), "r"(b1));
}

// ---------------- shared GEMM mainloop ----------------
struct GemmCtx {
    uint32_t sbase;
    int tid, wid, lid, wm, wn, r0c, c16, lrow, khalf;
};

__device__ __forceinline__ void gemm_main(
    const __half* __restrict__ A, const __half* __restrict__ B,
    int row0, int col0, const GemmCtx& cx, float acc[2][8][4])
{
#pragma unroll
    for (int mi = 0; mi < 2; ++mi)
#pragma unroll
        for (int ni = 0; ni < 8; ++ni)
#pragma unroll
            for (int j = 0; j < 4; ++j) acc[mi][ni][j] = 0.f;

    auto load_stage = [&](int buf, int it) {
        const int kt = it * BKE;
        const uint32_t sA = cx.sbase + buf * STAGE_BYTES;
        const uint32_t sB = sA + TILE_ELEMS * 2;
#pragma unroll
        for (int i = 0; i < 4; ++i) {
            const int r = cx.r0c + i * 32;
            const uint32_t so = (r * LDA + cx.c16 * 8) * 2;
            CP_ASYNC16(sA + so, A + (size_t)(row0 + r) * HH + kt + cx.c16 * 8);
            CP_ASYNC16(sB + so, B + (size_t)(col0 + r) * HH + kt + cx.c16 * 8);
        }
        CP_COMMIT();
    };

    load_stage(0, 0);
    load_stage(1, 1);

    int buf = 0, nb = 2;
    for (int it = 0; it < KITER; ++it) {
        CP_WAIT1();
        __syncthreads();
        if (it + 2 < KITER) load_stage(nb, it + 2);

        const uint32_t sA = cx.sbase + buf * STAGE_BYTES;
        const uint32_t sB = sA + TILE_ELEMS * 2;
#pragma unroll
        for (int k16 = 0; k16 < 4; ++k16) {
            uint32_t a[2][4], b[4][4];
#pragma unroll
            for (int mi = 0; mi < 2; ++mi)
                ldmx4(a[mi], sA + ((cx.wm + 16 * mi + cx.lrow) * LDA + k16 * 16 + cx.khalf) * 2);
#pragma unroll
            for (int nt = 0; nt < 4; ++nt)
                ldmx4(b[nt], sB + ((cx.wn + 16 * nt + cx.lrow) * LDA + k16 * 16 + cx.khalf) * 2);
#pragma unroll
            for (int mi = 0; mi < 2; ++mi)
#pragma unroll
                for (int nt = 0; nt < 4; ++nt) {
                    mma16816(acc[mi][2 * nt + 0], a[mi], b[nt][0], b[nt][2]);
                    mma16816(acc[mi][2 * nt + 1], a[mi], b[nt][1], b[nt][3]);
                }
        }
        buf = (buf + 1 == NSTAGE) ? 0 : buf + 1;
        nb = (nb + 1 == NSTAGE) ? 0 : nb + 1;
    }
    CP_WAIT0();
}

__device__ __forceinline__ GemmCtx make_ctx(const void* smem) {
    GemmCtx cx;
    cx.sbase = smem_u32(smem);
    cx.tid = threadIdx.x;
    cx.wid = cx.tid >> 5; cx.lid = cx.tid & 31;
    cx.wm = (cx.wid >> 1) * 32;
    cx.wn = (cx.wid & 1) * 64;
    cx.r0c = cx.tid >> 3;
    cx.c16 = cx.tid & 7;
    cx.lrow = cx.lid & 15;
    cx.khalf = (cx.lid >> 4) * 8;
    return cx;
}

// ================= fused k/v/r GEMM: grid.z selects which; fp16 output =================
__global__ void __launch_bounds__(256, 2)
mmagemm_kvr()
{
    extern __shared__ __half sm[];
    const GemmCtx cx = make_ctx(sm);
    const int z = blockIdx.z;
    const int row0 = blockIdx.y * BM;
    const int col0 = blockIdx.x * BN;
    const __half* A = &g_ax[z][0];
    const __half* B = &g_wt[z][0];
    __half* out = (z == 0) ? g_kh : (z == 1) ? g_vh : g_rh;

    float acc[2][8][4];
    gemm_main(A, B, row0, col0, cx, acc);

    const int erow = cx.wm + (cx.lid >> 2);
    const int ecol = cx.wn + (cx.lid & 3) * 2;
#pragma unroll
    for (int mi = 0; mi < 2; ++mi)
#pragma unroll
        for (int ni = 0; ni < 8; ++ni)
#pragma unroll
            for (int h = 0; h < 2; ++h) {
                const int r = row0 + erow + mi * 16 + h * 8;
                const int c = col0 + ecol + ni * 8;
                __half2 v = __floats2half2_rn(acc[mi][ni][h * 2 + 0], acc[mi][ni][h * 2 + 1]);
                *reinterpret_cast<__half2*>(out + (size_t)r * HH + c) = v;
            }
}

// ================= final GEMM: out = hidden + rw @ Wo^T =================
__global__ void __launch_bounds__(256, 2)
mmagemm_out(const float* __restrict__ addv, float* __restrict__ out)
{
    extern __shared__ __half sm[];
    const GemmCtx cx = make_ctx(sm);
    const int row0 = blockIdx.y * BM;
    const int col0 = blockIdx.x * BN;

    float acc[2][8][4];
    gemm_main(&g_rw[0], &g_wt[3][0], row0, col0, cx, acc);

    const int erow = cx.wm + (cx.lid >> 2);
    const int ecol = cx.wn + (cx.lid & 3) * 2;
#pragma unroll
    for (int mi = 0; mi < 2; ++mi)
#pragma unroll
        for (int ni = 0; ni < 8; ++ni)
#pragma unroll
            for (int h = 0; h < 2; ++h) {
                const int r = row0 + erow + mi * 16 + h * 8;
                const int c = col0 + ecol + ni * 8;
                const size_t o = (size_t)r * HH + c;
                float2 hv = *reinterpret_cast<const float2*>(addv + o);
                float2 v;
                v.x = acc[mi][ni][h * 2 + 0] + hv.x;
                v.y = acc[mi][ni][h * 2 + 1] + hv.y;
                *reinterpret_cast<float2*>(out + o) = v;
            }
}

// ================= split / transpose prep =================
__global__ void __launch_bounds__(256)
split_acts(const float* __restrict__ hidden, const float* __restrict__ sx,
           const float* __restrict__ tmk, const float* __restrict__ tmv,
           const float* __restrict__ tmr)
{
    const int idx = blockIdx.x * 256 + threadIdx.x;  // float4 index
    const int h4 = idx & (HH / 4 - 1);
    float4 hv = reinterpret_cast<const float4*>(hidden)[idx];
    float4 pv = (idx >= HH / 4) ? reinterpret_cast<const float4*>(hidden)[idx - HH / 4]
                                : reinterpret_cast<const float4*>(sx)[h4];
    const float* tms[3] = {tmk, tmv, tmr};
#pragma unroll
    for (int p = 0; p < 3; ++p) {
        float4 mv = reinterpret_cast<const float4*>(tms[p])[h4];
        union { __half b[4]; uint2 u; } Hh;
        Hh.b[0] = __float2half_rn(fmaf(hv.x - pv.x, mv.x, pv.x));
        Hh.b[1] = __float2half_rn(fmaf(hv.y - pv.y, mv.y, pv.y));
        Hh.b[2] = __float2half_rn(fmaf(hv.z - pv.z, mv.z, pv.z));
        Hh.b[3] = __float2half_rn(fmaf(hv.w - pv.w, mv.w, pv.w));
        *reinterpret_cast<uint2*>(&g_ax[p][(size_t)idx * 4]) = Hh.u;
    }
}

// W[K,N] -> W^T[N,K] fp16, all 4 weights in one launch (grid.z selects W)
__global__ void __launch_bounds__(256)
wtrans4(const float* __restrict__ W0, const float* __restrict__ W1,
        const float* __restrict__ W2, const float* __restrict__ W3)
{
    __shared__ float ts[32][33];
    const int z = blockIdx.z;
    const float* W = (z == 0) ? W0 : (z == 1) ? W1 : (z == 2) ? W2 : W3;
    __half* T = &g_wt[z][0];
    const int n0 = blockIdx.x * 32, k0 = blockIdx.y * 32;
    const int tx = threadIdx.x, ty = threadIdx.y;  // 32 x 8
#pragma unroll
    for (int i = 0; i < 4; ++i)
        ts[ty + i * 8][tx] = W[(size_t)(k0 + ty + i * 8) * HH + n0 + tx];
    __syncthreads();
#pragma unroll
    for (int i = 0; i < 4; ++i) {
        const size_t o = (size_t)(n0 + ty + i * 8) * HH + k0 + tx;
        T[o] = __float2half_rn(ts[tx][ty + i * 8]);
    }
}

// ================= WKV chunked scan (fp16 k/v/r inputs; single-exp forms) =================
// max-subtraction with one exp: q=max(x,y); exp(x-q),exp(y-q) = (1,e) or (e,1), e=exp(-|x-y|)
__global__ void scan_phaseA(const float* __restrict__ td)
{
    int h = blockIdx.x * blockDim.x + threadIdx.x;
    int c = blockIdx.y;
    float w = -expf(td[h]);
    float a = 0.f, b = 0.f, p = -1e30f;
    int t0 = c * CLEN;
    for (int t = t0; t < t0 + CLEN; ++t) {
        int idx = t * HH + h;
        float kk = __half2float(g_kh[idx]);
        float vv = __half2float(g_vh[idx]);
        float ww = w + p;
        float d = ww - kk;
        float e = __expf(-fabsf(d));
        float e1 = (d >= 0.f) ? 1.f : e;
        float e2 = (d >= 0.f) ? e : 1.f;
        a = e1 * a + e2 * vv;
        b = e1 * b + e2;
        p = fmaxf(ww, kk);
    }
    g_Sa[c * HH + h] = a;
    g_Sb[c * HH + h] = b;
    g_Sm[c * HH + h] = p;
}

__global__ void scan_phaseB(const float* __restrict__ td,
                            const float* __restrict__ aa0, const float* __restrict__ bb0,
                            const float* __restrict__ pp0, const float* __restrict__ hidden,
                            float* __restrict__ out)
{
    int h = blockIdx.x * blockDim.x + threadIdx.x;
    float w = -expf(td[h]);
    float wL = w * (float)CLEN;
    float a = aa0[h], b = bb0[h], p = pp0[h];
    for (int c = 0; c < NCHUNK; ++c) {
        g_Pa[c * HH + h] = a;
        g_Pb[c * HH + h] = b;
        g_Pp[c * HH + h] = p;
        float m = g_Sm[c * HH + h];
        float pd = p + wL;
        float d = pd - m;
        float e = __expf(-fabsf(d));
        float e1 = (d >= 0.f) ? 1.f : e;
        float e2 = (d >= 0.f) ? e : 1.f;
        a = e1 * a + e2 * g_Sa[c * HH + h];
        b = e1 * b + e2 * g_Sb[c * HH + h];
        p = fmaxf(pd, m);
    }
    out[TT * HH + h] = hidden[(TT - 1) * HH + h];
    out[TT * HH + HH + h] = a;
    out[TT * HH + 2 * HH + h] = b;
    out[TT * HH + 3 * HH + h] = p;
}

__global__ void scan_phaseC(const float* __restrict__ td, const float* __restrict__ tf)
{
    int h = blockIdx.x * blockDim.x + threadIdx.x;
    int c = blockIdx.y;
    float w = -expf(td[h]);
    float u = tf[h];
    float a = g_Pa[c * HH + h], b = g_Pb[c * HH + h], p = g_Pp[c * HH + h];
    int t0 = c * CLEN;
    for (int t = t0; t < t0 + CLEN; ++t) {
        int idx = t * HH + h;
        float kk = __half2float(g_kh[idx]);
        float vv = __half2float(g_vh[idx]);
        // output with bonus: q = max(p, u+kk)
        float ww = u + kk;
        float d1 = p - ww;
        float e = __expf(-fabsf(d1));
        float e1 = (d1 >= 0.f) ? 1.f : e;
        float e2 = (d1 >= 0.f) ? e : 1.f;
        float num = e1 * a + e2 * vv;
        float den = e1 * b + e2;
        // rw = sigmoid(r) * num/den = num / (den * (1 + exp(-r)))  [one reciprocal]
        float sr = 1.f + __expf(-__half2float(g_rh[idx]));
        g_rw[idx] = __float2half_rn(num * __frcp_rn(den * sr));
        // state update with decay: q2 = max(w+p, kk)
        float ww2 = w + p;
        float d2 = ww2 - kk;
        float f = __expf(-fabsf(d2));
        float f1 = (d2 >= 0.f) ? 1.f : f;
        float f2 = (d2 >= 0.f) ? f : 1.f;
        a = f1 * a + f2 * vv;
        b = f1 * b + f2;
        p = fmaxf(ww2, kk);
    }
}

extern "C" void kernel_launch(void* const* d_in, const int* in_sizes, int n_in,
                              void* d_out, int out_size)
{
    const float* hidden = (const float*)d_in[0];
    const float* sx     = (const float*)d_in[1];
    const float* aa     = (const float*)d_in[2];
    const float* bb     = (const float*)d_in[3];
    const float* pp     = (const float*)d_in[4];
    const float* td     = (const float*)d_in[5];
    const float* tf     = (const float*)d_in[6];
    const float* tmk    = (const float*)d_in[7];
    const float* tmv    = (const float*)d_in[8];
    const float* tmr    = (const float*)d_in[9];
    const float* Wk     = (const float*)d_in[10];
    const float* Wv     = (const float*)d_in[11];
    const float* Wr     = (const float*)d_in[12];
    const float* Wo     = (const float*)d_in[13];
    float* out = (float*)d_out;

    cudaFuncSetAttribute(mmagemm_kvr, cudaFuncAttributeMaxDynamicSharedMemorySize, GSMEM);
    cudaFuncSetAttribute(mmagemm_out, cudaFuncAttributeMaxDynamicSharedMemorySize, GSMEM);

    dim3 wgrid(HH / 32, HH / 32, 4), wblk(32, 8);
    wtrans4<<<wgrid, wblk>>>(Wk, Wv, Wr, Wo);
    split_acts<<<(TT * HH / 4) / 256, 256>>>(hidden, sx, tmk, tmv, tmr);

    dim3 gkvr(HH / BN, TT / BM, 3);
    mmagemm_kvr<<<gkvr, 256, GSMEM>>>();

    dim3 sgrid(HH / 256, NCHUNK);
    scan_phaseA<<<sgrid, 256>>>(td);
    scan_phaseB<<<HH / 256, 256>>>(td, aa, bb, pp, hidden, out);
    scan_phaseC<<<sgrid, 256>>>(td, tf);

    dim3 gg(HH / BN, TT / BM);
    mmagemm_out<<<gg, 256, GSMEM>>>(hidden, out);
}

// round 14
// speedup vs baseline: 1.2714x; 1.0368x over previous
#include <cuda_runtime.h>
#include <cuda_fp16.h>
#include <math.h>
#include <cstdint>

#define TT 8192
#define HH 2048
#define NCHUNK 128
#define CLEN 64

// GEMM tiling (R8 config: best measured; smem-crossbar-bound floor)
#define BM 128
#define BN 128
#define BKE 64
#define LDA 72
#define TILE_ELEMS (128 * LDA)
#define STAGE_BYTES (2 * TILE_ELEMS * 2)
#define NSTAGE 3
#define GSMEM (NSTAGE * STAGE_BYTES)       // 110592 -> 2 CTAs/SM
#define KITER (HH / BKE)                   // 32

// ---------------- scratch (device globals; allocation-free) ----------------
__device__ __half g_kh[TT * HH];
__device__ __half g_vh[TT * HH];
__device__ __half g_rh[TT * HH];
__device__ __half g_ax[3][TT * HH];
__device__ __half g_wt[4][HH * HH];
__device__ __half g_rw[TT * HH];
__device__ float g_Sa[NCHUNK * HH];
__device__ float g_Sb[NCHUNK * HH];
__device__ float g_Sm[NCHUNK * HH];
__device__ float g_Pa[NCHUNK * HH];
__device__ float g_Pb[NCHUNK * HH];
__device__ float g_Pp[NCHUNK * HH];

// ---------------- PTX helpers ----------------
__device__ __forceinline__ uint32_t smem_u32(const void* p) {
    uint32_t a;
    asm("{ .reg .u64 t; cvta.to.shared.u64 t, %1; cvt.u32.u64 %0, t; }" : "=r"(a) : "l"(p));
    return a;
}

#define CP_ASYNC16(dst, src) \
    asm volatile("cp.async.cg.shared.global [%0], [%1], 16;" :: "r"(dst), "l"(src))
#define CP_COMMIT() asm volatile("cp.async.commit_group;" ::: "memory")
#define CP_WAIT1() asm volatile("cp.async.wait_group 1;" ::: "memory")
#define CP_WAIT0() asm volatile("cp.async.wait_group 0;" ::: "memory")

__device__ __forceinline__ void ldmx4(uint32_t* r, uint32_t addr) {
    asm volatile("ldmatrix.sync.aligned.m8n8.x4.shared.b16 {%0,%1,%2,%3}, [%4];"
                 : "=r"(r[0]), "=r"(r[1]), "=r"(r[2]), "=r"(r[3]) : "r"(addr));
}

__device__ __forceinline__ void mma16816(float* d, const uint32_t* a, uint32_t b0, uint32_t b1) {
    asm volatile("mma.sync.aligned.m16n8k16.row.col.f32.f16.f16.f32 "
                 "{%0,%1,%2,%3}, {%4,%5,%6,%7}, {%8,%9}, {%0,%1,%2,%3};"
                 : "+f"(d[0]), "+f"(d[1]), "+f"(d[2]), "+f"(d[3])
                 : "r"(a[0]), "r"(a[1]), "r"(a[2]), "r"(a[3]), "r"(b0), "r"(b1));
}

// ---------------- shared GEMM mainloop ----------------
struct GemmCtx {
    uint32_t sbase;
    int tid, wid, lid, wm, wn, r0c, c16, lrow, khalf;
};

__device__ __forceinline__ void gemm_main(
    const __half* __restrict__ A, const __half* __restrict__ B,
    int row0, int col0, const GemmCtx& cx, float acc[2][8][4])
{
#pragma unroll
    for (int mi = 0; mi < 2; ++mi)
#pragma unroll
        for (int ni = 0; ni < 8; ++ni)
#pragma unroll
            for (int j = 0; j < 4; ++j) acc[mi][ni][j] = 0.f;

    auto load_stage = [&](int buf, int it) {
        const int kt = it * BKE;
        const uint32_t sA = cx.sbase + buf * STAGE_BYTES;
        const uint32_t sB = sA + TILE_ELEMS * 2;
#pragma unroll
        for (int i = 0; i < 4; ++i) {
            const int r = cx.r0c + i * 32;
            const uint32_t so = (r * LDA + cx.c16 * 8) * 2;
            CP_ASYNC16(sA + so, A + (size_t)(row0 + r) * HH + kt + cx.c16 * 8);
            CP_ASYNC16(sB + so, B + (size_t)(col0 + r) * HH + kt + cx.c16 * 8);
        }
        CP_COMMIT();
    };

    load_stage(0, 0);
    load_stage(1, 1);

    int buf = 0, nb = 2;
    for (int it = 0; it < KITER; ++it) {
        CP_WAIT1();
        __syncthreads();
        if (it + 2 < KITER) load_stage(nb, it + 2);

        const uint32_t sA = cx.sbase + buf * STAGE_BYTES;
        const uint32_t sB = sA + TILE_ELEMS * 2;
#pragma unroll
        for (int k16 = 0; k16 < 4; ++k16) {
            uint32_t a[2][4], b[4][4];
#pragma unroll
            for (int mi = 0; mi < 2; ++mi)
                ldmx4(a[mi], sA + ((cx.wm + 16 * mi + cx.lrow) * LDA + k16 * 16 + cx.khalf) * 2);
#pragma unroll
            for (int nt = 0; nt < 4; ++nt)
                ldmx4(b[nt], sB + ((cx.wn + 16 * nt + cx.lrow) * LDA + k16 * 16 + cx.khalf) * 2);
#pragma unroll
            for (int mi = 0; mi < 2; ++mi)
#pragma unroll
                for (int nt = 0; nt < 4; ++nt) {
                    mma16816(acc[mi][2 * nt + 0], a[mi], b[nt][0], b[nt][2]);
                    mma16816(acc[mi][2 * nt + 1], a[mi], b[nt][1], b[nt][3]);
                }
        }
        buf = (buf + 1 == NSTAGE) ? 0 : buf + 1;
        nb = (nb + 1 == NSTAGE) ? 0 : nb + 1;
    }
    CP_WAIT0();
}

__device__ __forceinline__ GemmCtx make_ctx(const void* smem) {
    GemmCtx cx;
    cx.sbase = smem_u32(smem);
    cx.tid = threadIdx.x;
    cx.wid = cx.tid >> 5; cx.lid = cx.tid & 31;
    cx.wm = (cx.wid >> 1) * 32;
    cx.wn = (cx.wid & 1) * 64;
    cx.r0c = cx.tid >> 3;
    cx.c16 = cx.tid & 7;
    cx.lrow = cx.lid & 15;
    cx.khalf = (cx.lid >> 4) * 8;
    return cx;
}

// ================= fused k/v/r GEMM =================
__global__ void __launch_bounds__(256, 2)
mmagemm_kvr()
{
    extern __shared__ __half sm[];
    const GemmCtx cx = make_ctx(sm);
    const int z = blockIdx.z;
    const int row0 = blockIdx.y * BM;
    const int col0 = blockIdx.x * BN;
    const __half* A = &g_ax[z][0];
    const __half* B = &g_wt[z][0];
    __half* out = (z == 0) ? g_kh : (z == 1) ? g_vh : g_rh;

    float acc[2][8][4];
    gemm_main(A, B, row0, col0, cx, acc);

    const int erow = cx.wm + (cx.lid >> 2);
    const int ecol = cx.wn + (cx.lid & 3) * 2;
#pragma unroll
    for (int mi = 0; mi < 2; ++mi)
#pragma unroll
        for (int ni = 0; ni < 8; ++ni)
#pragma unroll
            for (int h = 0; h < 2; ++h) {
                const int r = row0 + erow + mi * 16 + h * 8;
                const int c = col0 + ecol + ni * 8;
                __half2 v = __floats2half2_rn(acc[mi][ni][h * 2 + 0], acc[mi][ni][h * 2 + 1]);
                *reinterpret_cast<__half2*>(out + (size_t)r * HH + c) = v;
            }
}

// ================= final GEMM: out = hidden + rw @ Wo^T =================
__global__ void __launch_bounds__(256, 2)
mmagemm_out(const float* __restrict__ addv, float* __restrict__ out)
{
    extern __shared__ __half sm[];
    const GemmCtx cx = make_ctx(sm);
    const int row0 = blockIdx.y * BM;
    const int col0 = blockIdx.x * BN;

    float acc[2][8][4];
    gemm_main(&g_rw[0], &g_wt[3][0], row0, col0, cx, acc);

    const int erow = cx.wm + (cx.lid >> 2);
    const int ecol = cx.wn + (cx.lid & 3) * 2;
#pragma unroll
    for (int mi = 0; mi < 2; ++mi)
#pragma unroll
        for (int ni = 0; ni < 8; ++ni)
#pragma unroll
            for (int h = 0; h < 2; ++h) {
                const int r = row0 + erow + mi * 16 + h * 8;
                const int c = col0 + ecol + ni * 8;
                const size_t o = (size_t)r * HH + c;
                float2 hv = *reinterpret_cast<const float2*>(addv + o);
                float2 v;
                v.x = acc[mi][ni][h * 2 + 0] + hv.x;
                v.y = acc[mi][ni][h * 2 + 1] + hv.y;
                *reinterpret_cast<float2*>(out + o) = v;
            }
}

// ================= split / transpose prep =================
__global__ void __launch_bounds__(256)
split_acts(const float* __restrict__ hidden, const float* __restrict__ sx,
           const float* __restrict__ tmk, const float* __restrict__ tmv,
           const float* __restrict__ tmr)
{
    const int idx = blockIdx.x * 256 + threadIdx.x;  // float4 index
    const int h4 = idx & (HH / 4 - 1);
    float4 hv = reinterpret_cast<const float4*>(hidden)[idx];
    float4 pv = (idx >= HH / 4) ? reinterpret_cast<const float4*>(hidden)[idx - HH / 4]
                                : reinterpret_cast<const float4*>(sx)[h4];
    const float* tms[3] = {tmk, tmv, tmr};
#pragma unroll
    for (int p = 0; p < 3; ++p) {
        float4 mv = reinterpret_cast<const float4*>(tms[p])[h4];
        union { __half b[4]; uint2 u; } Hh;
        Hh.b[0] = __float2half_rn(fmaf(hv.x - pv.x, mv.x, pv.x));
        Hh.b[1] = __float2half_rn(fmaf(hv.y - pv.y, mv.y, pv.y));
        Hh.b[2] = __float2half_rn(fmaf(hv.z - pv.z, mv.z, pv.z));
        Hh.b[3] = __float2half_rn(fmaf(hv.w - pv.w, mv.w, pv.w));
        *reinterpret_cast<uint2*>(&g_ax[p][(size_t)idx * 4]) = Hh.u;
    }
}

// W[K,N] -> W^T[N,K] fp16
__global__ void __launch_bounds__(256)
wtrans4(const float* __restrict__ W0, const float* __restrict__ W1,
        const float* __restrict__ W2, const float* __restrict__ W3)
{
    __shared__ float ts[32][33];
    const int z = blockIdx.z;
    const float* W = (z == 0) ? W0 : (z == 1) ? W1 : (z == 2) ? W2 : W3;
    __half* T = &g_wt[z][0];
    const int n0 = blockIdx.x * 32, k0 = blockIdx.y * 32;
    const int tx = threadIdx.x, ty = threadIdx.y;  // 32 x 8
#pragma unroll
    for (int i = 0; i < 4; ++i)
        ts[ty + i * 8][tx] = W[(size_t)(k0 + ty + i * 8) * HH + n0 + tx];
    __syncthreads();
#pragma unroll
    for (int i = 0; i < 4; ++i) {
        const size_t o = (size_t)(n0 + ty + i * 8) * HH + k0 + tx;
        T[o] = __float2half_rn(ts[tx][ty + i * 8]);
    }
}

// ================= WKV chunked scan =================
// 2 channels per thread, __half2 loads; single-exp forms (same per-channel math)
__global__ void scan_phaseA(const float* __restrict__ td)
{
    int h2 = blockIdx.x * blockDim.x + threadIdx.x;   // pair index
    int h = h2 * 2;
    int c = blockIdx.y;
    float w0 = -expf(td[h]), w1 = -expf(td[h + 1]);
    float a0 = 0.f, b0 = 0.f, p0 = -1e30f;
    float a1 = 0.f, b1 = 0.f, p1 = -1e30f;
    int t0 = c * CLEN;
    for (int t = t0; t < t0 + CLEN; ++t) {
        size_t idx = (size_t)t * HH + h;
        float2 kk = __half22float2(*reinterpret_cast<const __half2*>(&g_kh[idx]));
        float2 vv = __half22float2(*reinterpret_cast<const __half2*>(&g_vh[idx]));
        {
            float ww = w0 + p0, d = ww - kk.x;
            float e = __expf(-fabsf(d));
            float e1 = (d >= 0.f) ? 1.f : e, e2 = (d >= 0.f) ? e : 1.f;
            a0 = e1 * a0 + e2 * vv.x; b0 = e1 * b0 + e2; p0 = fmaxf(ww, kk.x);
        }
        {
            float ww = w1 + p1, d = ww - kk.y;
            float e = __expf(-fabsf(d));
            float e1 = (d >= 0.f) ? 1.f : e, e2 = (d >= 0.f) ? e : 1.f;
            a1 = e1 * a1 + e2 * vv.y; b1 = e1 * b1 + e2; p1 = fmaxf(ww, kk.y);
        }
    }
    *reinterpret_cast<float2*>(&g_Sa[c * HH + h]) = make_float2(a0, a1);
    *reinterpret_cast<float2*>(&g_Sb[c * HH + h]) = make_float2(b0, b1);
    *reinterpret_cast<float2*>(&g_Sm[c * HH + h]) = make_float2(p0, p1);
}

// sequential chunk combine with register prefetch of next chunk's summaries
__global__ void scan_phaseB(const float* __restrict__ td,
                            const float* __restrict__ aa0, const float* __restrict__ bb0,
                            const float* __restrict__ pp0, const float* __restrict__ hidden,
                            float* __restrict__ out)
{
    int h = blockIdx.x * blockDim.x + threadIdx.x;
    float w = -expf(td[h]);
    float wL = w * (float)CLEN;
    float a = aa0[h], b = bb0[h], p = pp0[h];
    float sa = g_Sa[h], sb = g_Sb[h], sm = g_Sm[h];
    for (int c = 0; c < NCHUNK; ++c) {
        float nsa, nsb, nsm;
        if (c + 1 < NCHUNK) {                  // prefetch next chunk before using current
            nsa = g_Sa[(c + 1) * HH + h];
            nsb = g_Sb[(c + 1) * HH + h];
            nsm = g_Sm[(c + 1) * HH + h];
        }
        g_Pa[c * HH + h] = a;
        g_Pb[c * HH + h] = b;
        g_Pp[c * HH + h] = p;
        float pd = p + wL;
        float d = pd - sm;
        float e = __expf(-fabsf(d));
        float e1 = (d >= 0.f) ? 1.f : e, e2 = (d >= 0.f) ? e : 1.f;
        a = e1 * a + e2 * sa;
        b = e1 * b + e2 * sb;
        p = fmaxf(pd, sm);
        sa = nsa; sb = nsb; sm = nsm;
    }
    out[TT * HH + h] = hidden[(TT - 1) * HH + h];
    out[TT * HH + HH + h] = a;
    out[TT * HH + 2 * HH + h] = b;
    out[TT * HH + 3 * HH + h] = p;
}

__global__ void scan_phaseC(const float* __restrict__ td, const float* __restrict__ tf)
{
    int h2 = blockIdx.x * blockDim.x + threadIdx.x;
    int h = h2 * 2;
    int c = blockIdx.y;
    float w0 = -expf(td[h]), w1 = -expf(td[h + 1]);
    float u0 = tf[h], u1 = tf[h + 1];
    float2 Pa = *reinterpret_cast<const float2*>(&g_Pa[c * HH + h]);
    float2 Pb = *reinterpret_cast<const float2*>(&g_Pb[c * HH + h]);
    float2 Pp = *reinterpret_cast<const float2*>(&g_Pp[c * HH + h]);
    float a0 = Pa.x, b0 = Pb.x, p0 = Pp.x;
    float a1 = Pa.y, b1 = Pb.y, p1 = Pp.y;
    int t0 = c * CLEN;
    for (int t = t0; t < t0 + CLEN; ++t) {
        size_t idx = (size_t)t * HH + h;
        float2 kk = __half22float2(*reinterpret_cast<const __half2*>(&g_kh[idx]));
        float2 vv = __half22float2(*reinterpret_cast<const __half2*>(&g_vh[idx]));
        float2 rr = __half22float2(*reinterpret_cast<const __half2*>(&g_rh[idx]));
        float rw0, rw1;
        {
            float ww = u0 + kk.x, d1 = p0 - ww;
            float e = __expf(-fabsf(d1));
            float e1 = (d1 >= 0.f) ? 1.f : e, e2 = (d1 >= 0.f) ? e : 1.f;
            float num = e1 * a0 + e2 * vv.x;
            float den = e1 * b0 + e2;
            float sr = 1.f + __expf(-rr.x);
            rw0 = num * __frcp_rn(den * sr);
            float ww2 = w0 + p0, d2 = ww2 - kk.x;
            float f = __expf(-fabsf(d2));
            float f1 = (d2 >= 0.f) ? 1.f : f, f2 = (d2 >= 0.f) ? f : 1.f;
            a0 = f1 * a0 + f2 * vv.x; b0 = f1 * b0 + f2; p0 = fmaxf(ww2, kk.x);
        }
        {
            float ww = u1 + kk.y, d1 = p1 - ww;
            float e = __expf(-fabsf(d1));
            float e1 = (d1 >= 0.f) ? 1.f : e, e2 = (d1 >= 0.f) ? e : 1.f;
            float num = e1 * a1 + e2 * vv.y;
            float den = e1 * b1 + e2;
            float sr = 1.f + __expf(-rr.y);
            rw1 = num * __frcp_rn(den * sr);
            float ww2 = w1 + p1, d2 = ww2 - kk.y;
            float f = __expf(-fabsf(d2));
            float f1 = (d2 >= 0.f) ? 1.f : f, f2 = (d2 >= 0.f) ? f : 1.f;
            a1 = f1 * a1 + f2 * vv.y; b1 = f1 * b1 + f2; p1 = fmaxf(ww2, kk.y);
        }
        *reinterpret_cast<__half2*>(&g_rw[idx]) = __floats2half2_rn(rw0, rw1);
    }
}

extern "C" void kernel_launch(void* const* d_in, const int* in_sizes, int n_in,
                              void* d_out, int out_size)
{
    const float* hidden = (const float*)d_in[0];
    const float* sx     = (const float*)d_in[1];
    const float* aa     = (const float*)d_in[2];
    const float* bb     = (const float*)d_in[3];
    const float* pp     = (const float*)d_in[4];
    const float* td     = (const float*)d_in[5];
    const float* tf     = (const float*)d_in[6];
    const float* tmk    = (const float*)d_in[7];
    const float* tmv    = (const float*)d_in[8];
    const float* tmr    = (const float*)d_in[9];
    const float* Wk     = (const float*)d_in[10];
    const float* Wv     = (const float*)d_in[11];
    const float* Wr     = (const float*)d_in[12];
    const float* Wo     = (const float*)d_in[13];
    float* out = (float*)d_out;

    cudaFuncSetAttribute(mmagemm_kvr, cudaFuncAttributeMaxDynamicSharedMemorySize, GSMEM);
    cudaFuncSetAttribute(mmagemm_out, cudaFuncAttributeMaxDynamicSharedMemorySize, GSMEM);

    dim3 wgrid(HH / 32, HH / 32, 4), wblk(32, 8);
    wtrans4<<<wgrid, wblk>>>(Wk, Wv, Wr, Wo);
    split_acts<<<(TT * HH / 4) / 256, 256>>>(hidden, sx, tmk, tmv, tmr);

    dim3 gkvr(HH / BN, TT / BM, 3);
    mmagemm_kvr<<<gkvr, 256, GSMEM>>>();

    dim3 sgrid(HH / 2 / 256, NCHUNK);
    scan_phaseA<<<sgrid, 256>>>(td);
    scan_phaseB<<<HH / 256, 256>>>(td, aa, bb, pp, hidden, out);
    scan_phaseC<<<sgrid, 256>>>(td, tf);

    dim3 gg(HH / BN, TT / BM);
    mmagemm_out<<<gg, 256, GSMEM>>>(hidden, out);
}